// round 17
// baseline (speedup 1.0000x reference)
#include <cuda_runtime.h>
#include <cuda_bf16.h>
#include <stdint.h>

// Problem constants
#define B_FEAT 128
#define U_UNITS 100000
#define K_NBR 500
#define N_RUNS 10
#define N_PAIRS 124750.0
#define T2 64          // pair tile edge
#define NTP2 36        // 8*9/2 lower-tri tile pairs (incl diagonal)
#define YSTRIDE 132    // float row stride: 132 mod 32 == 4 -> conflict-free frags

typedef unsigned long long u64;

// Scratch (device globals; no allocation allowed)
__device__ float  g_Y[N_RUNS][K_NBR][B_FEAT];   // normalized, tf32-rounded
__device__ float2 g_P[N_RUNS][K_NBR];           // gathered positions
__device__ double g_part[N_RUNS * NTP2][5];     // per-block partial sums
__device__ int    g_done = 0;                   // finalize counter

struct Choice { int v[N_RUNS]; };
struct Wt     { float w[N_RUNS]; };

// ---------------------------------------------------------------------------
// Kernel 1: gather + center + normalize + round-to-tf32 (rna) feature cols
// ---------------------------------------------------------------------------
__global__ void prep_kernel(const float* __restrict__ feat,
                            const float* __restrict__ pos,
                            const int*   __restrict__ nbh,
                            Choice ch) {
    int u   = blockIdx.x;
    int run = blockIdx.y;
    int f   = threadIdx.x;
    int wid = f >> 5, lane = f & 31;

    int ind = __ldg(&nbh[ch.v[run] * K_NBR + u]);
    float v = __ldg(&feat[f * U_UNITS + ind]);

    __shared__ float ws[4];
    float s = v;
    #pragma unroll
    for (int o = 16; o > 0; o >>= 1) s += __shfl_xor_sync(0xFFFFFFFFu, s, o);
    if (lane == 0) ws[wid] = s;
    __syncthreads();
    float mean = (ws[0] + ws[1] + ws[2] + ws[3]) * (1.0f / B_FEAT);
    __syncthreads();

    float c = v - mean;
    float q = c * c;
    #pragma unroll
    for (int o = 16; o > 0; o >>= 1) q += __shfl_xor_sync(0xFFFFFFFFu, q, o);
    if (lane == 0) ws[wid] = q;
    __syncthreads();
    float inv = rsqrtf(ws[0] + ws[1] + ws[2] + ws[3]);

    float y = c * inv;
    uint32_t ytf;
    asm("cvt.rna.tf32.f32 %0, %1;" : "=r"(ytf) : "f"(y));
    g_Y[run][u][f] = __uint_as_float(ytf);
    if (f == 0) g_P[run][u] = make_float2(__ldg(&pos[ind * 2]), __ldg(&pos[ind * 2 + 1]));
}

// ---------------------------------------------------------------------------
// f32x2 packed helpers (sm_100+): two pairs per instruction
// ---------------------------------------------------------------------------
__device__ __forceinline__ u64 pk(float lo, float hi) {
    u64 r;
    asm("mov.b64 %0, {%1, %2};" : "=l"(r) : "r"(__float_as_uint(lo)), "r"(__float_as_uint(hi)));
    return r;
}
__device__ __forceinline__ void upk(u64 p, float& lo, float& hi) {
    uint32_t a, b;
    asm("mov.b64 {%0, %1}, %2;" : "=r"(a), "=r"(b) : "l"(p));
    lo = __uint_as_float(a); hi = __uint_as_float(b);
}
__device__ __forceinline__ u64 f2add(u64 a, u64 b) {
    u64 r; asm("add.rn.f32x2 %0, %1, %2;" : "=l"(r) : "l"(a), "l"(b)); return r;
}
__device__ __forceinline__ u64 f2mul(u64 a, u64 b) {
    u64 r; asm("mul.rn.f32x2 %0, %1, %2;" : "=l"(r) : "l"(a), "l"(b)); return r;
}
__device__ __forceinline__ u64 f2fma(u64 a, u64 b, u64 c) {
    u64 r; asm("fma.rn.f32x2 %0, %1, %2, %3;" : "=l"(r) : "l"(a), "l"(b), "l"(c)); return r;
}

#define F2_SIGN  0x8000000080000000ULL
#define F2_HALF  0x3F0000003F000000ULL
#define F2_15    0x3FC000003FC00000ULL
#define F2_ONE   0x3F8000003F800000ULL
#define F2_TWO   0x4000000040000000ULL
#define F2_RSQ   0x5f3759df5f3759dfULL
#define F2_RCP   0x7EF311C37EF311C3ULL
#define F2_SHM   0xFFFFFFFF7FFFFFFFULL

// packed ds = 1/(1+sqrt(s2)), MUFU-free, 2+2 Newton (~7e-6).
// 64-bit seed subs are borrow-free: s2<=200 and xpl<=15.3 keep lane bits
// below the seed constants. s2==0 lane resolves to ds≈1 (err 6e-6).
__device__ __forceinline__ u64 dist2_pk(u64 s2) {
    u64 h = f2mul(s2, F2_HALF);
    u64 y = F2_RSQ - ((s2 >> 1) & F2_SHM);
    u64 t = f2mul(h, y) ^ F2_SIGN;
    y = f2mul(y, f2fma(t, y, F2_15));
    t = f2mul(h, y) ^ F2_SIGN;
    y = f2mul(y, f2fma(t, y, F2_15));
    u64 d   = f2mul(s2, y);
    u64 xpl = f2add(d, F2_ONE);
    u64 nx  = xpl ^ F2_SIGN;
    u64 r   = F2_RCP - xpl;
    r = f2mul(r, f2fma(nx, r, F2_TWO));
    r = f2mul(r, f2fma(nx, r, F2_TWO));
    return r;
}

// ---------------------------------------------------------------------------
// Kernel 2: pair sums via tf32 mma.sync.m16n8k8 (T2=64, 8 warps 4x2, each
// warp 16x32). Packed-f32x2 epilogue; interior tiles skip masking entirely.
// ---------------------------------------------------------------------------
__global__ __launch_bounds__(256) void pair_kernel(float* __restrict__ out, Wt wt) {
    extern __shared__ char sraw[];
    float*  Ys = (float*)sraw;                   // Yi [64][132]
    float*  Yt = Ys + T2 * YSTRIDE;              // Yj [64][132]
    float2* Pi = (float2*)(Yt + T2 * YSTRIDE);
    float2* Pj = Pi + T2;

    int run = blockIdx.y;
    int t   = blockIdx.x;
    int ti = 0;
    while ((ti + 1) * (ti + 2) / 2 <= t) ti++;
    int tj = t - ti * (ti + 1) / 2;
    int i0 = ti * T2, j0 = tj * T2;

    int tid = threadIdx.x;

    for (int idx = tid; idx < T2 * 32; idx += 256) {
        int r = idx >> 5, c = idx & 31;
        int gi = i0 + r, gj = j0 + r;
        ((float4*)(Ys + r * YSTRIDE))[c] =
            (gi < K_NBR) ? ((const float4*)g_Y[run][gi])[c] : make_float4(0, 0, 0, 0);
        ((float4*)(Yt + r * YSTRIDE))[c] =
            (gj < K_NBR) ? ((const float4*)g_Y[run][gj])[c] : make_float4(0, 0, 0, 0);
    }
    if (tid < T2) {
        Pi[tid] = (i0 + tid < K_NBR) ? g_P[run][i0 + tid] : make_float2(0, 0);
    } else if (tid < 2 * T2) {
        int k = tid - T2;
        Pj[k] = (j0 + k < K_NBR) ? g_P[run][j0 + k] : make_float2(0, 0);
    }
    __syncthreads();

    int lane = tid & 31, w = tid >> 5;
    int wy = w >> 1, wx = w & 1;
    int g4 = lane >> 2, q4 = lane & 3;

    const float* Arow0 = Ys + (wy * 16 + g4) * YSTRIDE;
    const float* Bbase = Yt + (wx * 32 + g4) * YSTRIDE;

    float acc[4][4];
    #pragma unroll
    for (int nt = 0; nt < 4; nt++)
        #pragma unroll
        for (int e = 0; e < 4; e++) acc[nt][e] = 0.f;

    #pragma unroll
    for (int ks = 0; ks < 16; ks++) {
        int k0 = ks * 8;
        uint32_t a0 = __float_as_uint(Arow0[k0 + q4]);
        uint32_t a1 = __float_as_uint(Arow0[8 * YSTRIDE + k0 + q4]);
        uint32_t a2 = __float_as_uint(Arow0[k0 + q4 + 4]);
        uint32_t a3 = __float_as_uint(Arow0[8 * YSTRIDE + k0 + q4 + 4]);
        #pragma unroll
        for (int nt = 0; nt < 4; nt++) {
            uint32_t b0 = __float_as_uint(Bbase[nt * 8 * YSTRIDE + k0 + q4]);
            uint32_t b1 = __float_as_uint(Bbase[nt * 8 * YSTRIDE + k0 + q4 + 4]);
            asm volatile(
                "mma.sync.aligned.m16n8k8.row.col.f32.tf32.tf32.f32 "
                "{%0,%1,%2,%3}, {%4,%5,%6,%7}, {%8,%9}, {%0,%1,%2,%3};"
                : "+f"(acc[nt][0]), "+f"(acc[nt][1]), "+f"(acc[nt][2]), "+f"(acc[nt][3])
                : "r"(a0), "r"(a1), "r"(a2), "r"(a3), "r"(b0), "r"(b1));
        }
    }

    // ---------------- packed f32x2 epilogue ----------------
    // thread owns D rows {wy*16+g4, +8}, cols {wx*32+nt*8+2*q4, +1}
    int r0l = wy * 16 + g4;
    float2 pi0 = Pi[r0l], pi1 = Pi[r0l + 8];
    u64 pix[2] = { pk(pi0.x, pi0.x), pk(pi1.x, pi1.x) };
    u64 piy[2] = { pk(pi0.y, pi0.y), pk(pi1.y, pi1.y) };

    u64 sr2 = 0, sd2 = 0, srd2 = 0, srr2 = 0, sdd2 = 0;
    bool full = (ti != tj) && (i0 + T2 <= K_NBR);   // interior off-diagonal

    if (full) {
        #pragma unroll
        for (int nt = 0; nt < 4; nt++) {
            int c0l = wx * 32 + nt * 8 + 2 * q4;
            float4 pjq = ((const float4*)Pj)[c0l >> 1];
            u64 npjx = pk(pjq.x, pjq.z) ^ F2_SIGN;
            u64 npjy = pk(pjq.y, pjq.w) ^ F2_SIGN;
            #pragma unroll
            for (int rr = 0; rr < 2; rr++) {
                u64 dx = f2add(pix[rr], npjx);
                u64 dy = f2add(piy[rr], npjy);
                u64 s2 = f2fma(dy, dy, f2mul(dx, dx));
                u64 ds = dist2_pk(s2);
                u64 dp = pk(acc[nt][2 * rr], acc[nt][2 * rr + 1]);
                sr2  = f2add(sr2, dp);
                sd2  = f2add(sd2, ds);
                srd2 = f2fma(dp, ds, srd2);
                srr2 = f2fma(dp, dp, srr2);
                sdd2 = f2fma(ds, ds, sdd2);
            }
        }
    } else {
        #pragma unroll
        for (int nt = 0; nt < 4; nt++) {
            int c0l = wx * 32 + nt * 8 + 2 * q4;
            float4 pjq = ((const float4*)Pj)[c0l >> 1];
            u64 npjx = pk(pjq.x, pjq.z) ^ F2_SIGN;
            u64 npjy = pk(pjq.y, pjq.w) ^ F2_SIGN;
            #pragma unroll
            for (int rr = 0; rr < 2; rr++) {
                int gi  = i0 + r0l + rr * 8;
                int gj0 = j0 + c0l, gj1 = gj0 + 1;
                float m0 = (gi < K_NBR && gj0 < K_NBR && gi > gj0) ? 1.0f : 0.0f;
                float m1 = (gi < K_NBR && gj1 < K_NBR && gi > gj1) ? 1.0f : 0.0f;
                u64 mp = pk(m0, m1);
                u64 dx = f2add(pix[rr], npjx);
                u64 dy = f2add(piy[rr], npjy);
                u64 s2 = f2fma(dy, dy, f2mul(dx, dx));
                u64 ds = dist2_pk(s2);
                u64 dp = pk(acc[nt][2 * rr], acc[nt][2 * rr + 1]);
                u64 dm = f2mul(dp, mp);
                u64 rm = f2mul(ds, mp);
                sr2  = f2add(sr2, dm);
                sd2  = f2add(sd2, rm);
                srd2 = f2fma(dm, ds, srd2);
                srr2 = f2fma(dm, dp, srr2);
                sdd2 = f2fma(rm, ds, sdd2);
            }
        }
    }

    float la, lb;
    upk(sr2,  la, lb); float sr  = la + lb;
    upk(sd2,  la, lb); float sd  = la + lb;
    upk(srd2, la, lb); float srd = la + lb;
    upk(srr2, la, lb); float srr = la + lb;
    upk(sdd2, la, lb); float sdd = la + lb;

    // block reduce 5 sums
    #pragma unroll
    for (int off = 16; off > 0; off >>= 1) {
        sr  += __shfl_down_sync(0xFFFFFFFFu, sr,  off);
        sd  += __shfl_down_sync(0xFFFFFFFFu, sd,  off);
        srd += __shfl_down_sync(0xFFFFFFFFu, srd, off);
        srr += __shfl_down_sync(0xFFFFFFFFu, srr, off);
        sdd += __shfl_down_sync(0xFFFFFFFFu, sdd, off);
    }
    __shared__ float wsum[8][5];
    if (lane == 0) {
        wsum[w][0] = sr;  wsum[w][1] = sd;  wsum[w][2] = srd;
        wsum[w][3] = srr; wsum[w][4] = sdd;
    }
    __syncthreads();
    if (tid == 0) {
        double a0 = 0, a1 = 0, a2 = 0, a3 = 0, a4 = 0;
        #pragma unroll
        for (int ww = 0; ww < 8; ww++) {
            a0 += wsum[ww][0]; a1 += wsum[ww][1]; a2 += wsum[ww][2];
            a3 += wsum[ww][3]; a4 += wsum[ww][4];
        }
        double* p = g_part[run * NTP2 + t];
        p[0] = a0; p[1] = a1; p[2] = a2; p[3] = a3; p[4] = a4;
    }

    // ---- last-block finalize (unique-run count = gridDim.y) ----
    int nblocks = gridDim.x * gridDim.y;
    int nu = gridDim.y;
    __shared__ int isLast;
    if (tid == 0) {
        __threadfence();
        int done = atomicAdd(&g_done, 1);
        isLast = (done == nblocks - 1) ? 1 : 0;
    }
    __syncthreads();
    if (!isLast) return;

    __shared__ double red[50];
    if (tid < 5 * nu) {
        int rn = tid / 5, cp = tid % 5;
        double s = 0;
        for (int b2 = 0; b2 < NTP2; b2++) s += g_part[rn * NTP2 + b2][cp];
        red[tid] = s;
    }
    __syncthreads();
    __shared__ double lsum[N_RUNS];
    if (tid < nu) {
        double Sr  = red[tid * 5 + 0], Sd  = red[tid * 5 + 1], Srd = red[tid * 5 + 2];
        double Srr = red[tid * 5 + 3], Sdd = red[tid * 5 + 4];
        double num = Srd - Sr * Sd / N_PAIRS;
        double den = sqrt((Srr - Sr * Sr / N_PAIRS) * (Sdd - Sd * Sd / N_PAIRS));
        lsum[tid] = (double)wt.w[tid] * (1.0 - num / den) * 0.5;
    }
    __syncthreads();
    if (tid == 0) {
        double s = 0;
        for (int i = 0; i < nu; i++) s += lsum[i];
        out[0] = (float)s;          // weights already sum to 1
        g_done = 0;                 // reset for next graph replay
    }
}

// ---------------------------------------------------------------------------
// Host-side JAX threefry2x32: choice = randint(key(42),(10,),0,100)
// ---------------------------------------------------------------------------
static inline uint32_t rotl32(uint32_t x, int r) { return (x << r) | (x >> (32 - r)); }

static void threefry2x32(uint32_t k0, uint32_t k1, uint32_t c0, uint32_t c1,
                         uint32_t* o0, uint32_t* o1) {
    uint32_t ks0 = k0, ks1 = k1, ks2 = k0 ^ k1 ^ 0x1BD11BDAu;
    uint32_t x0 = c0 + ks0, x1 = c1 + ks1;
    const int rotA[4] = {13, 15, 26, 6};
    const int rotB[4] = {17, 29, 16, 24};
#define TF_ROUND4(R) do { for (int _i = 0; _i < 4; _i++) { \
        x0 += x1; x1 = rotl32(x1, (R)[_i]); x1 ^= x0; } } while (0)
    TF_ROUND4(rotA); x0 += ks1; x1 += ks2 + 1;
    TF_ROUND4(rotB); x0 += ks2; x1 += ks0 + 2;
    TF_ROUND4(rotA); x0 += ks0; x1 += ks1 + 3;
    TF_ROUND4(rotB); x0 += ks1; x1 += ks2 + 4;
    TF_ROUND4(rotA); x0 += ks2; x1 += ks0 + 5;
#undef TF_ROUND4
    *o0 = x0; *o1 = x1;
}

extern "C" void kernel_launch(void* const* d_in, const int* in_sizes, int n_in,
                              void* d_out, int out_size) {
    const float* feat = (const float*)d_in[0];
    const float* pos  = (const float*)d_in[1];
    const int*   nbh  = (const int*)d_in[2];

    uint32_t bits[N_RUNS];
    for (uint32_t i = 0; i < 5; i++) {
        uint32_t o0, o1;
        threefry2x32(0u, 42u, i, i + 5u, &o0, &o1);
        bits[i] = o0;
        bits[i + 5] = o1;
    }
    int choice[N_RUNS];
    for (int i = 0; i < N_RUNS; i++) {
        uint32_t b = bits[i];
        uint32_t hi = b >> 16, lo = b & 0xFFFFu;
        choice[i] = (int)(((hi % 100u) * 96u + (lo % 100u)) % 100u);
    }

    // dedupe runs: launch only unique neighborhoods, weight the average
    Choice ch; Wt wt;
    int nu = 0;
    for (int i = 0; i < N_RUNS; i++) {
        int f = -1;
        for (int k = 0; k < nu; k++) if (ch.v[k] == choice[i]) { f = k; break; }
        if (f >= 0) wt.w[f] += 1.0f / N_RUNS;
        else { ch.v[nu] = choice[i]; wt.w[nu] = 1.0f / N_RUNS; nu++; }
    }

    const int SMEM = 2 * T2 * YSTRIDE * (int)sizeof(float) + 2 * T2 * (int)sizeof(float2);
    cudaFuncSetAttribute(pair_kernel, cudaFuncAttributeMaxDynamicSharedMemorySize, SMEM);

    prep_kernel<<<dim3(K_NBR, nu), B_FEAT>>>(feat, pos, nbh, ch);
    pair_kernel<<<dim3(NTP2, nu), 256, SMEM>>>((float*)d_out, wt);
}